// round 1
// baseline (speedup 1.0000x reference)
#include <cuda_runtime.h>
#include <cuda_bf16.h>
#include <cstdint>

#define BATCH 8
#define NN    2048
#define DD    128
#define BK    64
#define LDT   72   // 64 + 8 pad halves; 144 B row stride: 16B-aligned, 4-bank shift/row

// Scratch (no allocation allowed in kernel_launch)
__device__ __nv_bfloat16 g_Hbf[BATCH * NN * DD];
__device__ float         g_hsq[BATCH * NN];
__device__ float         g_partials[2048];

// ---------------------------------------------------------------------------
// Prep: fp32 emb -> bf16 copy + per-node squared norm (fp32)
// ---------------------------------------------------------------------------
__global__ void prep_kernel(const float* __restrict__ emb) {
    int row = blockIdx.x;          // 0 .. BATCH*NN-1
    int d   = threadIdx.x;         // 0 .. 127
    float v = emb[(size_t)row * DD + d];
    g_Hbf[(size_t)row * DD + d] = __float2bfloat16(v);
    float sq = v * v;
    #pragma unroll
    for (int o = 16; o > 0; o >>= 1) sq += __shfl_down_sync(0xffffffffu, sq, o);
    __shared__ float s[4];
    if ((d & 31) == 0) s[d >> 5] = sq;
    __syncthreads();
    if (d == 0) g_hsq[row] = s[0] + s[1] + s[2] + s[3];
}

// ---------------------------------------------------------------------------
// m16n8k16 bf16 MMA, fp32 accumulate
// ---------------------------------------------------------------------------
__device__ __forceinline__ void mma16816(float* c, const unsigned* a, const unsigned* b) {
    asm volatile(
        "mma.sync.aligned.m16n8k16.row.col.f32.bf16.bf16.f32 "
        "{%0,%1,%2,%3}, {%4,%5,%6,%7}, {%8,%9}, {%0,%1,%2,%3};\n"
        : "+f"(c[0]), "+f"(c[1]), "+f"(c[2]), "+f"(c[3])
        : "r"(a[0]), "r"(a[1]), "r"(a[2]), "r"(a[3]), "r"(b[0]), "r"(b[1]));
}

// ---------------------------------------------------------------------------
// Main: per 128x128 adj tile, gram via tensor cores, fused adj*relu(sqdist)
// grid (16, 16, 8) = (m-tiles, n-tiles, batch), 256 threads (8 warps, 2x4)
// ---------------------------------------------------------------------------
__global__ __launch_bounds__(256, 2) void main_kernel(const float* __restrict__ adj) {
    __shared__ __align__(16) __nv_bfloat16 sHn[128 * LDT];
    __shared__ __align__(16) __nv_bfloat16 sHm[128 * LDT];
    __shared__ float s_hsqn[128], s_hsqm[128];
    __shared__ float s_red[8];

    const int b   = blockIdx.z;
    const int bn0 = blockIdx.y * 128;
    const int bm0 = blockIdx.x * 128;
    const int tid  = threadIdx.x;
    const int lane = tid & 31;
    const int w    = tid >> 5;
    const int wr   = (w >> 2) * 64;  // warp row origin within tile
    const int wc   = (w & 3) * 32;   // warp col origin within tile

    if (tid < 128) s_hsqn[tid]       = g_hsq[b * NN + bn0 + tid];
    else           s_hsqm[tid - 128] = g_hsq[b * NN + bm0 + (tid - 128)];

    float acc[4][4][4];
    #pragma unroll
    for (int i = 0; i < 4; ++i)
        #pragma unroll
        for (int j = 0; j < 4; ++j)
            #pragma unroll
            for (int k = 0; k < 4; ++k) acc[i][j][k] = 0.f;

    const __nv_bfloat16* Hn = g_Hbf + ((size_t)(b * NN + bn0)) * DD;
    const __nv_bfloat16* Hm = g_Hbf + ((size_t)(b * NN + bm0)) * DD;

    #pragma unroll
    for (int kc = 0; kc < 2; ++kc) {
        __syncthreads();
        const uint4* srcn = (const uint4*)(Hn + kc * BK);  // 8 uint4 per row chunk
        const uint4* srcm = (const uint4*)(Hm + kc * BK);
        #pragma unroll
        for (int i = 0; i < 4; ++i) {
            int idx = tid + i * 256;          // 0..1023
            int r = idx >> 3, c4 = idx & 7;
            *(uint4*)&sHn[r * LDT + c4 * 8] = srcn[r * 16 + c4]; // global row = 16 uint4
            *(uint4*)&sHm[r * LDT + c4 * 8] = srcm[r * 16 + c4];
        }
        __syncthreads();

        #pragma unroll
        for (int kk = 0; kk < BK; kk += 16) {
            unsigned afr[4][4], bfr[4][2];
            #pragma unroll
            for (int i = 0; i < 4; ++i) {
                int r = wr + i * 16 + (lane >> 2);
                int c = kk + (lane & 3) * 2;
                afr[i][0] = *(const unsigned*)&sHn[r * LDT + c];
                afr[i][1] = *(const unsigned*)&sHn[(r + 8) * LDT + c];
                afr[i][2] = *(const unsigned*)&sHn[r * LDT + c + 8];
                afr[i][3] = *(const unsigned*)&sHn[(r + 8) * LDT + c + 8];
            }
            #pragma unroll
            for (int j = 0; j < 4; ++j) {
                int m = wc + j * 8 + (lane >> 2);
                int k = kk + (lane & 3) * 2;
                bfr[j][0] = *(const unsigned*)&sHm[m * LDT + k];
                bfr[j][1] = *(const unsigned*)&sHm[m * LDT + k + 8];
            }
            #pragma unroll
            for (int i = 0; i < 4; ++i)
                #pragma unroll
                for (int j = 0; j < 4; ++j)
                    mma16816(acc[i][j], afr[i], bfr[j]);
        }
    }

    // Fused adj * relu(sqdist) using accumulator lane layout
    float esum = 0.f;
    const int r_l = wr + (lane >> 2);
    const int c_l = wc + (lane & 3) * 2;
    const float* adjp = adj + ((size_t)b * NN + bn0 + r_l) * NN + bm0 + c_l;
    #pragma unroll
    for (int i = 0; i < 4; ++i) {
        #pragma unroll
        for (int j = 0; j < 4; ++j) {
            const float* p = adjp + (size_t)(i * 16) * NN + j * 8;
            float2 a0 = *(const float2*)p;
            float2 a1 = *(const float2*)(p + (size_t)8 * NN);
            int rl = wr + i * 16 + (lane >> 2);
            int cl = wc + j * 8 + (lane & 3) * 2;
            float hn0 = s_hsqn[rl], hn1 = s_hsqn[rl + 8];
            float hm0 = s_hsqm[cl], hm1 = s_hsqm[cl + 1];
            esum += a0.x * fmaxf(hn0 + hm0 - 2.f * acc[i][j][0], 0.f);
            esum += a0.y * fmaxf(hn0 + hm1 - 2.f * acc[i][j][1], 0.f);
            esum += a1.x * fmaxf(hn1 + hm0 - 2.f * acc[i][j][2], 0.f);
            esum += a1.y * fmaxf(hn1 + hm1 - 2.f * acc[i][j][3], 0.f);
        }
    }
    #pragma unroll
    for (int o = 16; o > 0; o >>= 1) esum += __shfl_down_sync(0xffffffffu, esum, o);
    if (lane == 0) s_red[w] = esum;
    __syncthreads();
    if (tid == 0) {
        float t = 0.f;
        #pragma unroll
        for (int i = 0; i < 8; ++i) t += s_red[i];
        g_partials[(blockIdx.z * 16 + blockIdx.y) * 16 + blockIdx.x] = t;
    }
}

// ---------------------------------------------------------------------------
// Deterministic final reduce in double
// ---------------------------------------------------------------------------
__global__ void reduce_kernel(float* __restrict__ out) {
    int tid = threadIdx.x;
    double s = 0.0;
    for (int i = tid; i < 2048; i += 256) s += (double)g_partials[i];
    #pragma unroll
    for (int o = 16; o > 0; o >>= 1) s += __shfl_down_sync(0xffffffffu, s, o);
    __shared__ double sm[8];
    if ((tid & 31) == 0) sm[tid >> 5] = s;
    __syncthreads();
    if (tid == 0) {
        double t = 0.0;
        #pragma unroll
        for (int i = 0; i < 8; ++i) t += sm[i];
        out[0] = (float)(t / (double)(BATCH * NN));
    }
}

// ---------------------------------------------------------------------------
extern "C" void kernel_launch(void* const* d_in, const int* in_sizes, int n_in,
                              void* d_out, int out_size) {
    // adj is the big input (8*2048*2048), node_emb the small one (8*2048*128)
    const float* adj = (const float*)d_in[0];
    const float* emb = (const float*)d_in[1];
    if (n_in >= 2 && in_sizes[0] < in_sizes[1]) {
        adj = (const float*)d_in[1];
        emb = (const float*)d_in[0];
    }

    prep_kernel<<<BATCH * NN, DD>>>(emb);
    dim3 grid(16, 16, 8);
    main_kernel<<<grid, 256>>>(adj);
    reduce_kernel<<<1, 256>>>((float*)d_out);
}

// round 2
// speedup vs baseline: 1.2828x; 1.2828x over previous
#include <cuda_runtime.h>
#include <cuda_bf16.h>
#include <cstdint>

#define BATCH 8
#define NN    2048
#define DD    128
#define BK    64
#define LDT   72   // 64 + 8 pad halves; 144 B row stride: 16B-aligned, 4-bank shift/row
#define NPAIR 136  // 16*17/2 triangular tile pairs

// Scratch (no allocation allowed in kernel_launch)
__device__ __nv_bfloat16 g_Hbf[BATCH * NN * DD];
__device__ float         g_hsq[BATCH * NN];
__device__ float         g_partials[BATCH * NPAIR];

// ---------------------------------------------------------------------------
// Prep: warp-per-row, float4 loads, no block sync.
// grid 2048 x 256 threads (8 warps = 8 rows per block)
// ---------------------------------------------------------------------------
__global__ __launch_bounds__(256) void prep_kernel(const float* __restrict__ emb) {
    const int w    = threadIdx.x >> 5;
    const int lane = threadIdx.x & 31;
    const int row  = blockIdx.x * 8 + w;
    float4 v = ((const float4*)(emb + (size_t)row * DD))[lane];
    __nv_bfloat162 p0 = __float22bfloat162_rn(make_float2(v.x, v.y));
    __nv_bfloat162 p1 = __float22bfloat162_rn(make_float2(v.z, v.w));
    uint2 st;
    st.x = *(unsigned*)&p0;
    st.y = *(unsigned*)&p1;
    ((uint2*)(g_Hbf + (size_t)row * DD))[lane] = st;
    float sq = v.x * v.x + v.y * v.y + v.z * v.z + v.w * v.w;
    #pragma unroll
    for (int o = 16; o > 0; o >>= 1) sq += __shfl_down_sync(0xffffffffu, sq, o);
    if (lane == 0) g_hsq[row] = sq;
}

// ---------------------------------------------------------------------------
// m16n8k16 bf16 MMA, fp32 accumulate
// ---------------------------------------------------------------------------
__device__ __forceinline__ void mma16816(float* c, const unsigned* a, const unsigned* b) {
    asm volatile(
        "mma.sync.aligned.m16n8k16.row.col.f32.bf16.bf16.f32 "
        "{%0,%1,%2,%3}, {%4,%5,%6,%7}, {%8,%9}, {%0,%1,%2,%3};\n"
        : "+f"(c[0]), "+f"(c[1]), "+f"(c[2]), "+f"(c[3])
        : "r"(a[0]), "r"(a[1]), "r"(a[2]), "r"(a[3]), "r"(b[0]), "r"(b[1]));
}

// ---------------------------------------------------------------------------
// Main: symmetric-pair tiles. For pair (ti<=tj), compute gram tile once and
// apply BOTH adj[ti,tj] and adj[tj,ti]^T (sq_dist is symmetric).
// grid (NPAIR, BATCH), 256 threads (8 warps, 2x4 warp grid over 128x128 tile)
// ---------------------------------------------------------------------------
__global__ __launch_bounds__(256, 2) void main_kernel(const float* __restrict__ adj) {
    __shared__ __align__(16) __nv_bfloat16 sHn[128 * LDT];
    __shared__ __align__(16) __nv_bfloat16 sHm[128 * LDT];
    __shared__ float s_hsqn[128], s_hsqm[128];
    __shared__ float s_red[8];

    // triangular decode: p = tj*(tj+1)/2 + ti, ti <= tj
    const int p = blockIdx.x;
    int tj = (int)((sqrtf(8.f * (float)p + 1.f) - 1.f) * 0.5f);
    while ((tj + 1) * (tj + 2) / 2 <= p) ++tj;
    while (tj * (tj + 1) / 2 > p) --tj;
    const int ti = p - tj * (tj + 1) / 2;

    const int b   = blockIdx.y;
    const int bn0 = ti * 128;   // row tile (n index)
    const int bm0 = tj * 128;   // col tile (m index)
    const bool offd = (ti != tj);

    const int tid  = threadIdx.x;
    const int lane = tid & 31;
    const int w    = tid >> 5;
    const int wr   = (w >> 2) * 64;  // warp row origin within tile
    const int wc   = (w & 3) * 32;   // warp col origin within tile

    if (tid < 128) s_hsqn[tid]       = g_hsq[b * NN + bn0 + tid];
    else           s_hsqm[tid - 128] = g_hsq[b * NN + bm0 + (tid - 128)];

    float acc[4][4][4];
    #pragma unroll
    for (int i = 0; i < 4; ++i)
        #pragma unroll
        for (int j = 0; j < 4; ++j)
            #pragma unroll
            for (int k = 0; k < 4; ++k) acc[i][j][k] = 0.f;

    const __nv_bfloat16* Hn = g_Hbf + ((size_t)(b * NN + bn0)) * DD;
    const __nv_bfloat16* Hm = g_Hbf + ((size_t)(b * NN + bm0)) * DD;

    #pragma unroll
    for (int kc = 0; kc < 2; ++kc) {
        __syncthreads();
        const uint4* srcn = (const uint4*)(Hn + kc * BK);
        const uint4* srcm = (const uint4*)(Hm + kc * BK);
        #pragma unroll
        for (int i = 0; i < 4; ++i) {
            int idx = tid + i * 256;          // 0..1023
            int r = idx >> 3, c4 = idx & 7;
            *(uint4*)&sHn[r * LDT + c4 * 8] = srcn[r * 16 + c4];
            *(uint4*)&sHm[r * LDT + c4 * 8] = srcm[r * 16 + c4];
        }
        __syncthreads();

        #pragma unroll
        for (int kk = 0; kk < BK; kk += 16) {
            unsigned afr[4][4], bfr[4][2];
            #pragma unroll
            for (int i = 0; i < 4; ++i) {
                int r = wr + i * 16 + (lane >> 2);
                int c = kk + (lane & 3) * 2;
                afr[i][0] = *(const unsigned*)&sHn[r * LDT + c];
                afr[i][1] = *(const unsigned*)&sHn[(r + 8) * LDT + c];
                afr[i][2] = *(const unsigned*)&sHn[r * LDT + c + 8];
                afr[i][3] = *(const unsigned*)&sHn[(r + 8) * LDT + c + 8];
            }
            #pragma unroll
            for (int j = 0; j < 4; ++j) {
                int m = wc + j * 8 + (lane >> 2);
                int k = kk + (lane & 3) * 2;
                bfr[j][0] = *(const unsigned*)&sHm[m * LDT + k];
                bfr[j][1] = *(const unsigned*)&sHm[m * LDT + k + 8];
            }
            #pragma unroll
            for (int i = 0; i < 4; ++i)
                #pragma unroll
                for (int j = 0; j < 4; ++j)
                    mma16816(acc[i][j], afr[i], bfr[j]);
        }
    }

    // Fused epilogue: sd = relu(hsq_n + hsq_m - 2g); weight = adj[n,m] (+ adj[m,n] if offd)
    float esum = 0.f;
    const int r_l = wr + (lane >> 2);        // row within tile for this lane
    const int c_l = wc + (lane & 3) * 2;     // col within tile for this lane
    const float* adjA = adj + ((size_t)b * NN + bn0 + r_l) * NN + bm0 + c_l;
    const float* adjT = adj + ((size_t)b * NN + bm0 + c_l) * NN + bn0 + r_l;
    #pragma unroll
    for (int i = 0; i < 4; ++i) {
        #pragma unroll
        for (int j = 0; j < 4; ++j) {
            const float* pA = adjA + (size_t)(i * 16) * NN + j * 8;
            float2 a0 = *(const float2*)pA;
            float2 a1 = *(const float2*)(pA + (size_t)8 * NN);
            float w00 = a0.x, w01 = a0.y, w10 = a1.x, w11 = a1.y;
            if (offd) {
                // transposed tile: element (row = c, col = r) pairs with sd(r, c)
                const float* pT = adjT + (size_t)(j * 8) * NN + i * 16;
                w00 += pT[0];                        // (c,   r)
                w01 += pT[NN];                       // (c+1, r)
                w10 += pT[8];                        // (c,   r+8)
                w11 += pT[NN + 8];                   // (c+1, r+8)
            }
            int rl = wr + i * 16 + (lane >> 2);
            int cl = wc + j * 8 + (lane & 3) * 2;
            float hn0 = s_hsqn[rl], hn1 = s_hsqn[rl + 8];
            float hm0 = s_hsqm[cl], hm1 = s_hsqm[cl + 1];
            esum += w00 * fmaxf(hn0 + hm0 - 2.f * acc[i][j][0], 0.f);
            esum += w01 * fmaxf(hn0 + hm1 - 2.f * acc[i][j][1], 0.f);
            esum += w10 * fmaxf(hn1 + hm0 - 2.f * acc[i][j][2], 0.f);
            esum += w11 * fmaxf(hn1 + hm1 - 2.f * acc[i][j][3], 0.f);
        }
    }
    #pragma unroll
    for (int o = 16; o > 0; o >>= 1) esum += __shfl_down_sync(0xffffffffu, esum, o);
    if (lane == 0) s_red[w] = esum;
    __syncthreads();
    if (tid == 0) {
        float t = 0.f;
        #pragma unroll
        for (int i = 0; i < 8; ++i) t += s_red[i];
        g_partials[blockIdx.y * NPAIR + blockIdx.x] = t;
    }
}

// ---------------------------------------------------------------------------
// Deterministic final reduce in double
// ---------------------------------------------------------------------------
__global__ void reduce_kernel(float* __restrict__ out) {
    int tid = threadIdx.x;
    double s = 0.0;
    for (int i = tid; i < BATCH * NPAIR; i += 256) s += (double)g_partials[i];
    #pragma unroll
    for (int o = 16; o > 0; o >>= 1) s += __shfl_down_sync(0xffffffffu, s, o);
    __shared__ double sm[8];
    if ((tid & 31) == 0) sm[tid >> 5] = s;
    __syncthreads();
    if (tid == 0) {
        double t = 0.0;
        #pragma unroll
        for (int i = 0; i < 8; ++i) t += sm[i];
        out[0] = (float)(t / (double)(BATCH * NN));
    }
}

// ---------------------------------------------------------------------------
extern "C" void kernel_launch(void* const* d_in, const int* in_sizes, int n_in,
                              void* d_out, int out_size) {
    const float* adj = (const float*)d_in[0];
    const float* emb = (const float*)d_in[1];
    if (n_in >= 2 && in_sizes[0] < in_sizes[1]) {
        adj = (const float*)d_in[1];
        emb = (const float*)d_in[0];
    }

    prep_kernel<<<BATCH * NN / 8, 256>>>(emb);
    dim3 grid(NPAIR, BATCH);
    main_kernel<<<grid, 256>>>(adj);
    reduce_kernel<<<1, 256>>>((float*)d_out);
}